// round 10
// baseline (speedup 1.0000x reference)
#include <cuda_runtime.h>
#include <math.h>

#define BSZ 4096
#define HB  128
#define TD  768
#define NS  16        // K-splits for Gram partials (4096/16 = 256 per split)
#define KCH 256

// ---------------- scratch (__device__ globals; no allocation) ----------------
static __device__ __align__(16) float g_ln[BSZ * HB];          // normalized logits (2 MB)
static __device__ __align__(16) float g_tn[BSZ * TD];          // normalized teacher (12.6 MB)
static __device__ float g_qpart[BSZ];                          // per-row quant partial
static __device__ float g_dpart[32 * BSZ];                     // per-coltile denom partials
static __device__ float g_pr[BSZ];                             // per-row contrastive loss
static __device__ __align__(16) float g_gt[NS * TD * TD];      // T^T T partials
static __device__ __align__(16) float g_m [NS * HB * TD];      // A^T T partials
static __device__ __align__(16) float g_ga[NS * HB * HB];      // A^T A partials
static __device__ float g_fro[3 * 64];                         // frobenius block partials
static __device__ int   g_mmode;                               // mask dtype: 0=u8 1=i32 2=f32

// ---------------- mask dtype detection via guaranteed diagonal ----------------
// positive_mask includes eye => mask[i][i] is True for ALL i. Exactly one of the
// three interpretations (uint8 / int32 / float32) will satisfy that for 256
// sampled i; the wrong ones hit quasi-random elements (density ~0.002) and fail
// with overwhelming probability. All sampled reads stay within the smallest
// possible buffer (u8: 16.7MB): max index 255*4096+255 elements -> 4.2MB as i32.
__global__ __launch_bounds__(256) void k_detect(const void* __restrict__ m)
{
    int t = threadIdx.x;
    size_t idx = (size_t)t * BSZ + t;
    const unsigned char* m8 = (const unsigned char*)m;
    const int*  m32 = (const int*)m;
    const float* mf = (const float*)m;
    int ok8  = (m8 [idx] != 0);
    int ok32 = (m32[idx] != 0);
    int okf  = (mf [idx] != 0.0f);
    int a8  = __syncthreads_and(ok8);
    int a32 = __syncthreads_and(ok32);
    int af  = __syncthreads_and(okf);
    if (t == 0) g_mmode = a32 ? 1 : (a8 ? 0 : (af ? 2 : 1));
}

// ---------------- normalize logits + quantization partial ----------------
__global__ __launch_bounds__(128) void k_norm_logits(const float* __restrict__ logits)
{
    int r = blockIdx.x;
    int t = threadIdx.x;
    float x = logits[(size_t)r * HB + t];
    float ss = x * x;
#pragma unroll
    for (int off = 16; off > 0; off >>= 1) ss += __shfl_down_sync(0xffffffffu, ss, off);
    __shared__ float sw[4];
    if ((t & 31) == 0) sw[t >> 5] = ss;
    __syncthreads();
    float n2 = sw[0] + sw[1] + sw[2] + sw[3];
    float inv = 1.0f / fmaxf(sqrtf(n2), 1e-12f);
    g_ln[(size_t)r * HB + t] = x * inv;

    float q = fabsf(fabsf(x) - 1.0f);
#pragma unroll
    for (int off = 16; off > 0; off >>= 1) q += __shfl_down_sync(0xffffffffu, q, off);
    __shared__ float sq[4];
    if ((t & 31) == 0) sq[t >> 5] = q;
    __syncthreads();
    if (t == 0) g_qpart[r] = sq[0] + sq[1] + sq[2] + sq[3];
}

// ---------------- normalize teacher ----------------
__global__ __launch_bounds__(256) void k_norm_teacher(const float* __restrict__ te)
{
    int r = blockIdx.x;
    int t = threadIdx.x;
    const float* row = te + (size_t)r * TD;
    float x0 = row[t], x1 = row[t + 256], x2 = row[t + 512];
    float ss = x0 * x0 + x1 * x1 + x2 * x2;
#pragma unroll
    for (int off = 16; off > 0; off >>= 1) ss += __shfl_down_sync(0xffffffffu, ss, off);
    __shared__ float sw[8];
    if ((t & 31) == 0) sw[t >> 5] = ss;
    __syncthreads();
    float n2 = sw[0] + sw[1] + sw[2] + sw[3] + sw[4] + sw[5] + sw[6] + sw[7];
    float inv = 1.0f / fmaxf(sqrtf(n2), 1e-12f);
    float* dst = g_tn + (size_t)r * TD;
    dst[t] = x0 * inv; dst[t + 256] = x1 * inv; dst[t + 512] = x2 * inv;
}

// ---------------- sim GEMM fused with exp + per-coltile denominator partials ---
// grid (32, 32), block 256, tile 128x128, K=128. No sim materialization.
__global__ __launch_bounds__(256) void k_sim()
{
    __shared__ float As[32][132];
    __shared__ float Bs[32][132];
    const int tid = threadIdx.x;
    const int tx = tid & 15, ty = tid >> 4;
    const int rowBase = blockIdx.y * 128;
    const int colBase = blockIdx.x * 128;

    float acc[8][8];
#pragma unroll
    for (int i = 0; i < 8; i++)
#pragma unroll
        for (int j = 0; j < 8; j++) acc[i][j] = 0.0f;

    for (int k0 = 0; k0 < HB; k0 += 32) {
#pragma unroll
        for (int l = 0; l < 4; l++) {
            int idx = tid + l * 256;       // float4 id 0..1023
            int r  = idx >> 3;             // 0..127
            int k4 = idx & 7;              // 0..7
            float4 va = *(const float4*)&g_ln[(size_t)(rowBase + r) * HB + k0 + k4 * 4];
            As[k4 * 4 + 0][r] = va.x; As[k4 * 4 + 1][r] = va.y;
            As[k4 * 4 + 2][r] = va.z; As[k4 * 4 + 3][r] = va.w;
            float4 vb = *(const float4*)&g_ln[(size_t)(colBase + r) * HB + k0 + k4 * 4];
            Bs[k4 * 4 + 0][r] = vb.x; Bs[k4 * 4 + 1][r] = vb.y;
            Bs[k4 * 4 + 2][r] = vb.z; Bs[k4 * 4 + 3][r] = vb.w;
        }
        __syncthreads();
#pragma unroll
        for (int k = 0; k < 32; k++) {
            float a[8], b[8];
#pragma unroll
            for (int u = 0; u < 8; u++) a[u] = As[k][ty * 8 + u];
#pragma unroll
            for (int u = 0; u < 8; u++) b[u] = Bs[k][tx * 8 + u];
#pragma unroll
            for (int i = 0; i < 8; i++)
#pragma unroll
                for (int j = 0; j < 8; j++) acc[i][j] = fmaf(a[i], b[j], acc[i][j]);
        }
        __syncthreads();
    }

    // epilogue: d = sum_j exp(5*cos - 5) excluding diagonal; reduce over tx lanes
#pragma unroll
    for (int i = 0; i < 8; i++) {
        int row = rowBase + ty * 8 + i;
        float d = 0.0f;
#pragma unroll
        for (int j = 0; j < 8; j++) {
            int col = colBase + tx * 8 + j;
            float e = __expf(fmaf(acc[i][j], 5.0f, -5.0f));
            if (col != row) d += e;
        }
#pragma unroll
        for (int off = 8; off > 0; off >>= 1)
            d += __shfl_down_sync(0xffffffffu, d, off, 16);
        if (tx == 0) g_dpart[(size_t)blockIdx.x * BSZ + row] = d;
    }
}

// ---------------- per-row: combine denom partials + positives via direct dots --
// one block (128 thr) per row. Positives are ~9/row; each found positive gets a
// fresh 128-length dot product against g_ln (L2-resident).
__global__ __launch_bounds__(128) void k_row(const void* __restrict__ mask)
{
    int r = blockIdx.x;
    int t = threadIdx.x;
    int mode = g_mmode;

    float d = (t < 32) ? g_dpart[(size_t)t * BSZ + r] : 0.0f;

    float p = 0.0f, c = 0.0f;
    const float4* a4 = (const float4*)(g_ln + (size_t)r * HB);
    size_t rowoff = (size_t)r * BSZ;
    for (int col = t; col < BSZ; col += 128) {
        bool pos;
        if (mode == 1)      pos = ((const int*)mask)[rowoff + col] != 0;
        else if (mode == 0) pos = ((const unsigned char*)mask)[rowoff + col] != 0;
        else                pos = ((const float*)mask)[rowoff + col] != 0.0f;
        if (pos) {
            const float4* b4 = (const float4*)(g_ln + (size_t)col * HB);
            float s = 0.0f;
#pragma unroll
            for (int k = 0; k < 32; k++) {
                float4 av = a4[k], bv = b4[k];
                s += av.x * bv.x + av.y * bv.y + av.z * bv.z + av.w * bv.w;
            }
            p += 5.0f * s;
            c += 1.0f;
        }
    }

    __shared__ float sd[128], sp[128], sc[128];
    sd[t] = d; sp[t] = p; sc[t] = c;
    __syncthreads();
    for (int off = 64; off > 0; off >>= 1) {
        if (t < off) {
            sd[t] += sd[t + off];
            sp[t] += sp[t + off];
            sc[t] += sc[t + off];
        }
        __syncthreads();
    }
    if (t == 0)
        g_pr[r] = logf(sd[0]) + 5.0f - sp[0] / fmaxf(sc[0], 1.0f);
}

// ---------------- generic Gram partial: Cpart[z] = A^T B over K chunk ----------
__global__ __launch_bounds__(256) void k_gram(const float* __restrict__ A_in,
                                              const float* __restrict__ B_in,
                                              int CA, int CB, int sym, int tag)
{
    if (sym && (int)blockIdx.x < (int)blockIdx.y) return;
    const float* A  = A_in ? A_in : (const float*)g_tn;
    const float* Bm = B_in ? B_in : (const float*)g_tn;
    float* Cpart = (tag == 0) ? g_gt : (tag == 1) ? g_m : g_ga;

    __shared__ float As[32][132];
    __shared__ float Bs[32][132];
    const int tid = threadIdx.x;
    const int tx = tid & 15, ty = tid >> 4;
    const int p0 = blockIdx.y * 128, q0 = blockIdx.x * 128;
    const int kBase = blockIdx.z * KCH;

    float acc[8][8];
#pragma unroll
    for (int i = 0; i < 8; i++)
#pragma unroll
        for (int j = 0; j < 8; j++) acc[i][j] = 0.0f;

    for (int kk = 0; kk < KCH; kk += 32) {
#pragma unroll
        for (int l = 0; l < 4; l++) {
            int idx = tid + l * 256;
            int i  = idx >> 5;
            int c4 = idx & 31;
            *(float4*)&As[i][c4 * 4] =
                *(const float4*)&A [(size_t)(kBase + kk + i) * CA + p0 + c4 * 4];
            *(float4*)&Bs[i][c4 * 4] =
                *(const float4*)&Bm[(size_t)(kBase + kk + i) * CB + q0 + c4 * 4];
        }
        __syncthreads();
#pragma unroll
        for (int k = 0; k < 32; k++) {
            float a[8], b[8];
#pragma unroll
            for (int u = 0; u < 8; u++) a[u] = As[k][ty * 8 + u];
#pragma unroll
            for (int u = 0; u < 8; u++) b[u] = Bs[k][tx * 8 + u];
#pragma unroll
            for (int i = 0; i < 8; i++)
#pragma unroll
                for (int j = 0; j < 8; j++) acc[i][j] = fmaf(a[i], b[j], acc[i][j]);
        }
        __syncthreads();
    }

    size_t outBase = (size_t)blockIdx.z * CA * CB;
#pragma unroll
    for (int i = 0; i < 8; i++) {
        int row = p0 + ty * 8 + i;
        float* dst = Cpart + outBase + (size_t)row * CB + q0 + tx * 8;
        *(float4*)&dst[0] = make_float4(acc[i][0], acc[i][1], acc[i][2], acc[i][3]);
        *(float4*)&dst[4] = make_float4(acc[i][4], acc[i][5], acc[i][6], acc[i][7]);
    }
}

// ---------------- reduce split-K partials -> Frobenius norm^2 partials ----------
__global__ __launch_bounds__(256) void k_fro(int tag)
{
    int CA = (tag == 0) ? TD : HB;
    int CB = (tag == 2) ? HB : TD;
    int sym = (tag == 0);
    const float* Cpart = (tag == 0) ? g_gt : (tag == 1) ? g_m : g_ga;
    size_t E = (size_t)CA * CB;

    float local = 0.0f;
    for (size_t e = (size_t)blockIdx.x * blockDim.x + threadIdx.x; e < E;
         e += (size_t)gridDim.x * blockDim.x) {
        int p = (int)(e / CB), q = (int)(e % CB);
        if (sym && p > q) continue;
        float s = 0.0f;
#pragma unroll
        for (int z = 0; z < NS; z++) s += Cpart[(size_t)z * E + e];
        float w = (sym && p != q) ? 2.0f : 1.0f;
        local += w * s * s;
    }
    __shared__ float sm[256];
    sm[threadIdx.x] = local;
    __syncthreads();
    for (int off = 128; off > 0; off >>= 1) {
        if (threadIdx.x < off) sm[threadIdx.x] += sm[threadIdx.x + off];
        __syncthreads();
    }
    if (threadIdx.x == 0) g_fro[tag * 64 + blockIdx.x] = sm[0];
}

// ---------------- final combine ----------------
__global__ __launch_bounds__(256) void k_final(float* __restrict__ out)
{
    __shared__ double sm[256];
    __shared__ double res[5];
    int t = threadIdx.x;
    for (int stage = 0; stage < 5; stage++) {
        double a = 0.0;
        if (stage == 0) {
            for (int i = t; i < BSZ; i += 256) a += (double)g_qpart[i];
        } else if (stage == 1) {
            for (int i = t; i < BSZ; i += 256) a += (double)g_pr[i];
        } else {
            if (t < 64) a = (double)g_fro[(stage - 2) * 64 + t];
        }
        sm[t] = a;
        __syncthreads();
        for (int off = 128; off > 0; off >>= 1) {
            if (t < off) sm[t] += sm[t + off];
            __syncthreads();
        }
        if (t == 0) res[stage] = sm[0];
        __syncthreads();
    }
    if (t == 0) {
        double quant_sum = res[0];
        double cont_sum  = res[1];
        double froGT     = res[2];
        double froM      = res[3];
        double froGA     = res[4];
        double loss_cont = cont_sum / (double)BSZ;
        double loss_dist = (froGA / (128.0 * 128.0) - 2.0 * froM / 128.0 + froGT)
                           / ((double)BSZ * (double)BSZ);
        double loss_q    = quant_sum / ((double)BSZ * (double)HB);
        out[0] = (float)(loss_cont + 0.5 * loss_dist + 0.01 * loss_q);
    }
}

// ---------------- launch ----------------
extern "C" void kernel_launch(void* const* d_in, const int* in_sizes, int n_in,
                              void* d_out, int out_size)
{
    (void)in_sizes; (void)n_in; (void)out_size;
    const float* logits   = (const float*)d_in[0];
    const float* hash     = (const float*)d_in[1];
    const float* teacher  = (const float*)d_in[2];
    const void*  mask     = (const void*)d_in[3];
    float* out = (float*)d_out;

    k_detect<<<1, 256>>>(mask);
    k_norm_logits<<<BSZ, 128>>>(logits);
    k_norm_teacher<<<BSZ, 256>>>(teacher);

    k_sim<<<dim3(32, 32), 256>>>();
    k_row<<<BSZ, 128>>>(mask);

    // G_T = Tn^T Tn (768x768, symmetric -> upper tiles only)
    k_gram<<<dim3(6, 6, NS), 256>>>(nullptr, nullptr, TD, TD, 1, 0);
    // M = hash^T Tn (128x768)
    k_gram<<<dim3(6, 1, NS), 256>>>(hash, nullptr, HB, TD, 0, 1);
    // G_A = hash^T hash (128x128)
    k_gram<<<dim3(1, 1, NS), 256>>>(hash, hash, HB, HB, 0, 2);

    k_fro<<<64, 256>>>(0);
    k_fro<<<64, 256>>>(1);
    k_fro<<<64, 256>>>(2);

    k_final<<<1, 256>>>(out);
}